// round 11
// baseline (speedup 1.0000x reference)
#include <cuda_runtime.h>
#include <cuda_fp16.h>
#include <cstddef>
#include <cstdint>

// ---------------- problem constants ----------------
#define Bsz   32
#define CINc  16
#define Hh    32
#define Ww    128
#define Oc    128
#define NTOT  512          // 128 channels x 4 gates, n = ch*4 + gate
#define ASTR  168          // A half-stride (84 words; 8-row LDSM banks distinct)
#define BSTR  152          // B half-stride (76 words; 8-row LDSM banks distinct)
#define THREADS 512

// ---------------- shared memory layout (bytes) ----------------
// A rows: 0-31 top buf0, 32-63 top buf1, 64-95 left buf0, 96-127 left buf1
// (left buffers carry h cols 0-127 and x cols 128-143)
#define OFF_B     0
#define SZ_B      (NTOT * BSTR * 2)            // 155648
#define OFF_A     (OFF_B + SZ_B)               // 155648
#define SZ_A      (128 * ASTR * 2)             // 43008
#define OFF_BIAS  (OFF_A + SZ_A)               // 198656
#define SZ_BIAS   (5 * Oc * 4)                 // 2560
#define SMEM_TOTAL (OFF_BIAS + SZ_BIAS)        // 201216

// transpose tile stride (halves); 69 words odd -> conflict-free strided reads
#define TTS 138

// ---------------- global scratch ----------------
// g_hbuf: canonical [bid][w][b][ch]
// g_cbuf: thread-packed [bid][w][p*2048 + tid*4 + nt]
__device__ __align__(256) __half  g_hbuf[(size_t)128 * 128 * 32 * 128];
__device__ __align__(256) float   g_cbuf[(size_t)128 * 128 * 32 * 128];
__device__ unsigned               g_pw[128][16];     // per-(row, warp) progress

// ---------------- helpers ----------------
__device__ __forceinline__ float tnhf(float x) {
    float y;
    asm("tanh.approx.f32 %0, %1;" : "=f"(y) : "f"(x));
    return y;
}
__device__ __forceinline__ float sigf(float x) {
    return fmaf(tnhf(0.5f * x), 0.5f, 0.5f);
}
__device__ __forceinline__ unsigned ld_acq(const unsigned* p) {
    unsigned v;
    asm volatile("ld.acquire.gpu.global.b32 %0, [%1];" : "=r"(v) : "l"(p));
    return v;
}
__device__ __forceinline__ void st_rel(unsigned* p, unsigned v) {
    asm volatile("st.release.gpu.global.b32 [%0], %1;" :: "l"(p), "r"(v) : "memory");
}
__device__ __forceinline__ void mma16816(float* c, const unsigned* a, unsigned b0, unsigned b1) {
    asm volatile(
        "mma.sync.aligned.m16n8k16.row.col.f32.f16.f16.f32 "
        "{%0,%1,%2,%3}, {%4,%5,%6,%7}, {%8,%9}, {%0,%1,%2,%3};"
        : "+f"(c[0]), "+f"(c[1]), "+f"(c[2]), "+f"(c[3])
        : "r"(a[0]), "r"(a[1]), "r"(a[2]), "r"(a[3]), "r"(b0), "r"(b1));
}
__device__ __forceinline__ void ldsm_x4(unsigned* r, unsigned addr) {
    asm volatile(
        "ldmatrix.sync.aligned.m8n8.x4.shared.b16 {%0,%1,%2,%3}, [%4];"
        : "=r"(r[0]), "=r"(r[1]), "=r"(r[2]), "=r"(r[3]) : "r"(addr));
}

__global__ void init_progress_kernel() {
    int i = threadIdx.x + blockIdx.x * blockDim.x;
    if (i < 128 * 16) (&g_pw[0][0])[i] = 0u;
}

// ---------------- main persistent kernel: one CTA per (direction, row) ----------------
__global__ void __launch_bounds__(THREADS, 1) mdlstm_kernel(
    const float* __restrict__ x,
    const float* __restrict__ w_ii, const float* __restrict__ w_hi, const float* __restrict__ b_i,
    const float* __restrict__ w_if, const float* __restrict__ w_hf, const float* __restrict__ b_f,
    const float* __restrict__ w_ig, const float* __restrict__ w_hg, const float* __restrict__ b_g,
    const float* __restrict__ w_io, const float* __restrict__ w_ho, const float* __restrict__ b_o,
    const float* __restrict__ wsum, const float* __restrict__ biasv,
    float* __restrict__ out)
{
    extern __shared__ char smem[];
    __half* sB    = reinterpret_cast<__half*>(smem + OFF_B);
    __half* sA    = reinterpret_cast<__half*>(smem + OFF_A);
    float*  sBias = reinterpret_cast<float*>(smem + OFF_BIAS);

    const int tid  = threadIdx.x;
    const int lane = tid & 31;
    const int wid  = tid >> 5;          // 0..15
    const int bid  = blockIdx.x;
    const int d    = bid >> 5;
    const int r    = bid & 31;
    const bool fx  = (d & 1) != 0;
    const bool fy  = (d & 2) != 0;
    const int  ph  = fy ? (Hh - 1 - r) : r;

    // ---- stage weights: sB[n][k], n = ch*4 + gate ----
    {
        const float* whArr[4] = {w_hi, w_hf, w_hg, w_ho};
        const float* wiArr[4] = {w_ii, w_if, w_ig, w_io};
        for (int gate = 0; gate < 4; ++gate) {
            const float* wh = whArr[gate] + (size_t)d * Oc * Oc;
            for (int idx = tid; idx < Oc * Oc; idx += THREADS) {
                int ch = idx >> 7, k = idx & 127;
                sB[(ch * 4 + gate) * BSTR + k] = __float2half(wh[idx]);
            }
            const float* wi = wiArr[gate] + (size_t)d * Oc * CINc;
            for (int idx = tid; idx < Oc * CINc; idx += THREADS) {
                int ch = idx >> 4, k = idx & 15;
                sB[(ch * 4 + gate) * BSTR + 128 + k] = __float2half(wi[idx]);
            }
        }
        const float* bArr[4] = {b_i, b_f, b_g, b_o};
        sBias[tid] = bArr[tid >> 7][(size_t)d * Oc + (tid & 127)];
        if (tid < 128) sBias[512 + tid] = biasv[(size_t)d * Oc + tid];
        // zero left buf0 h cols (read at w=0)
        for (int idx = tid; idx < 32 * 128; idx += THREADS) {
            int b = idx >> 7, c = idx & 127;
            sA[(64 + b) * ASTR + c] = __float2half(0.f);
        }
        if (r == 0) {   // h_top = 0 forever: zero both top buffers
            for (int idx = tid; idx < 64 * 128; idx += THREADS) {
                int b = idx >> 7, c = idx & 127;
                sA[b * ASTR + c] = __float2half(0.f);
            }
        }
    }
    const float ws0 = wsum[d * 2 + 0];
    const float ws1 = wsum[d * 2 + 1];

    const int g = lane >> 2, t = lane & 3;
    const bool oddt = (t & 1) != 0;

    // per-thread epilogue ownership: ch = chB + nt*2 (nt 0..3), bb = bbB + p*16
    const int chB = (wid << 3) + (t >> 1);
    const int bbB = g + (oddt ? 8 : 0);
    const int n0  = wid << 5;                        // warp's 32 n-cols
    const int sx_b = tid >> 4, sx_ci = tid & 15;     // h_top/x staging map

    // ldmatrix per-lane address roles
    const unsigned sAu = (unsigned)__cvta_generic_to_shared(sA);
    const unsigned sBu = (unsigned)__cvta_generic_to_shared(sB);
    const int aro  = (lane & 7) + ((lane >> 3) & 1) * 8;
    const int ako  = (lane >> 4) * 8;
    const unsigned aAtop0  = sAu + (unsigned)((aro * ASTR + ako) * 2);                 // +tb*32 rows
    const unsigned aAleft0 = sAu + (unsigned)(((64 + aro) * ASTR + ako) * 2);          // +cur*32 rows
    const unsigned aBU     = sBu + (unsigned)(((n0 + ((lane >> 4) & 1) * 8 + (lane & 7)) * BSTR
                                               + ((lane >> 3) & 1) * 8) * 2);

    float cleft[2][4];
#pragma unroll
    for (int p = 0; p < 2; ++p)
#pragma unroll
        for (int nt = 0; nt < 4; ++nt) cleft[p][nt] = 0.f;

    unsigned availH = 0, availC = 0;
    const unsigned* flagH = (r > 0) ? &g_pw[bid - 1][tid & 15] : nullptr;
    const unsigned* flagC = (r > 0) ? &g_pw[bid - 1][wid] : nullptr;

    const float* xrow = x + (size_t)tid * (Hh * Ww) + (size_t)ph * Ww;
    const int xm = fx ? 3 : 0;

    // prologue: stage x(0) into left buf0 x-cols
    float4 xq = *reinterpret_cast<const float4*>(xrow + (fx ? 124 : 0));
    {
        const int e = 0 ^ xm;
        float s01 = (e & 1) ? xq.y : xq.x;
        float s23 = (e & 1) ? xq.w : xq.z;
        sA[(64 + sx_b) * ASTR + 128 + sx_ci] = __float2half((e & 2) ? s23 : s01);
    }
    __syncthreads();

#pragma unroll 1
    for (int w = 0; w < Ww; ++w) {
        const int cur = w & 1, nxt = cur ^ 1, tb = w & 1;
        const size_t rowoff = ((size_t)bid * Ww + w) * (Bsz * Oc);
        const size_t topoff = rowoff - (size_t)Ww * (Bsz * Oc);

        // ---- head: poll matching producer warps, fetch h_top/c_top, stage h_top ----
        float ctop_[2][4];
        if (r > 0) {
            if (availH <= (unsigned)w) {
                availH = ld_acq(flagH);
                while (availH <= (unsigned)w) { __nanosleep(32); availH = ld_acq(flagH); }
            }
            if (availC <= (unsigned)w) {
                availC = ld_acq(flagC);
                while (availC <= (unsigned)w) { __nanosleep(32); availC = ld_acq(flagC); }
            }
            uint4 htop_v = *reinterpret_cast<const uint4*>(g_hbuf + topoff + (size_t)tid * 8);
            float4 q0 = *reinterpret_cast<const float4*>(g_cbuf + topoff + (tid << 2));
            float4 q1 = *reinterpret_cast<const float4*>(g_cbuf + topoff + 2048 + (tid << 2));
            ctop_[0][0] = q0.x; ctop_[0][1] = q0.y; ctop_[0][2] = q0.z; ctop_[0][3] = q0.w;
            ctop_[1][0] = q1.x; ctop_[1][1] = q1.y; ctop_[1][2] = q1.z; ctop_[1][3] = q1.w;
            // double-buffered top staging: safe pre-barrier (other buffer is live)
            *reinterpret_cast<uint4*>(sA + (tb * 32 + sx_b) * ASTR + sx_ci * 8) = htop_v;
        } else {
#pragma unroll
            for (int p = 0; p < 2; ++p)
#pragma unroll
                for (int nt = 0; nt < 4; ++nt) ctop_[p][nt] = 0.f;
        }
        __syncthreads();   // S_A — the ONLY CTA barrier in the step

        const unsigned aAleftU = aAleft0 + (unsigned)(cur * (32 * ASTR * 2));
        const unsigned aAtopU  = aAtop0  + (unsigned)(tb  * (32 * ASTR * 2));

        // ================= pass L: LEFT branch (left[cur]; k=8 = x cols) =================
        float htp[2][4];
        {
            float acc[2][4][4];
#pragma unroll
            for (int mt = 0; mt < 2; ++mt)
#pragma unroll
                for (int nt = 0; nt < 4; ++nt)
#pragma unroll
                    for (int q = 0; q < 4; ++q) acc[mt][nt][q] = 0.f;

#pragma unroll
            for (int k = 0; k < 9; ++k) {
                unsigned a0[4], a1[4], bp0[4], bp1[4];
                ldsm_x4(a0, aAleftU + (unsigned)(k * 32));
                ldsm_x4(a1, aAleftU + (unsigned)(16 * ASTR * 2 + k * 32));
                ldsm_x4(bp0, aBU + (unsigned)(k * 32));
                ldsm_x4(bp1, aBU + (unsigned)(16 * BSTR * 2 + k * 32));
                mma16816(acc[0][0], a0, bp0[0], bp0[1]);
                mma16816(acc[0][1], a0, bp0[2], bp0[3]);
                mma16816(acc[0][2], a0, bp1[0], bp1[1]);
                mma16816(acc[0][3], a0, bp1[2], bp1[3]);
                mma16816(acc[1][0], a1, bp0[0], bp0[1]);
                mma16816(acc[1][1], a1, bp0[2], bp0[3]);
                mma16816(acc[1][2], a1, bp1[0], bp1[1]);
                mma16816(acc[1][3], a1, bp1[2], bp1[3]);
            }
#pragma unroll
            for (int p = 0; p < 2; ++p) {
#pragma unroll
                for (int nt = 0; nt < 4; ++nt) {
                    float* c1 = acc[p][nt];
                    float rA = __shfl_xor_sync(0xffffffffu, oddt ? c1[0] : c1[2], 1);
                    float rB = __shfl_xor_sync(0xffffffffu, oddt ? c1[1] : c1[3], 1);
                    float pi, pf, pg, po;
                    if (!oddt) { pi = c1[0]; pf = c1[1]; pg = rA;    po = rB; }
                    else       { pi = rA;    pf = rB;    pg = c1[2]; po = c1[3]; }
                    const int ch = chB + nt * 2;
                    const float i1 = sigf(pi + sBias[ch]);
                    const float f1 = sigf(pf + sBias[128 + ch]);
                    const float g1 = tnhf(pg + sBias[256 + ch]);
                    const float o1 = sigf(po + sBias[384 + ch]);
                    const float cn1 = f1 * cleft[p][nt] + i1 * g1;
                    htp[p][nt]   = o1 * tnhf(cn1);
                    cleft[p][nt] = cn1;                 // cn1 carrier
                }
            }
        }

        // ================= pass T: TOP branch (top[tb]; k=8 from left[cur] x cols) ========
        {
            float acc[2][4][4];
#pragma unroll
            for (int mt = 0; mt < 2; ++mt)
#pragma unroll
                for (int nt = 0; nt < 4; ++nt)
#pragma unroll
                    for (int q = 0; q < 4; ++q) acc[mt][nt][q] = 0.f;

#pragma unroll
            for (int k = 0; k < 9; ++k) {
                const unsigned ab = (k < 8) ? (aAtopU + (unsigned)(k * 32))
                                            : (aAleftU + (unsigned)(8 * 32));
                unsigned a0[4], a1[4], bp0[4], bp1[4];
                ldsm_x4(a0, ab);
                ldsm_x4(a1, ab + (unsigned)(16 * ASTR * 2));
                ldsm_x4(bp0, aBU + (unsigned)(k * 32));
                ldsm_x4(bp1, aBU + (unsigned)(16 * BSTR * 2 + k * 32));
                mma16816(acc[0][0], a0, bp0[0], bp0[1]);
                mma16816(acc[0][1], a0, bp0[2], bp0[3]);
                mma16816(acc[0][2], a0, bp1[0], bp1[1]);
                mma16816(acc[0][3], a0, bp1[2], bp1[3]);
                mma16816(acc[1][0], a1, bp0[0], bp0[1]);
                mma16816(acc[1][1], a1, bp0[2], bp0[3]);
                mma16816(acc[1][2], a1, bp1[0], bp1[1]);
                mma16816(acc[1][3], a1, bp1[2], bp1[3]);
            }
#pragma unroll
            for (int p = 0; p < 2; ++p) {
#pragma unroll
                for (int nt = 0; nt < 4; ++nt) {
                    float* c0 = acc[p][nt];
                    float rA = __shfl_xor_sync(0xffffffffu, oddt ? c0[0] : c0[2], 1);
                    float rB = __shfl_xor_sync(0xffffffffu, oddt ? c0[1] : c0[3], 1);
                    float pi, pf, pg, po;
                    if (!oddt) { pi = c0[0]; pf = c0[1]; pg = rA;    po = rB; }
                    else       { pi = rA;    pf = rB;    pg = c0[2]; po = c0[3]; }
                    const int ch = chB + nt * 2;
                    const float i0 = sigf(pi + sBias[ch]);
                    const float f0 = sigf(pf + sBias[128 + ch]);
                    const float g0 = tnhf(pg + sBias[256 + ch]);
                    const float o0 = sigf(po + sBias[384 + ch]);
                    const float cn0 = f0 * ctop_[p][nt] + i0 * g0;
                    const float h0  = o0 * tnhf(cn0);

                    const float bv = sBias[512 + ch];
                    const float ct = fmaf(ws0, cn0, fmaf(ws1, cleft[p][nt], bv));
                    const float ht = fmaf(ws0, h0,  fmaf(ws1, htp[p][nt],  bv));

                    cleft[p][nt] = ct;
                    const int bb = bbB + p * 16;
                    sA[(64 + nxt * 32 + bb) * ASTR + ch] = __float2half(ht);
                }
            }
        }

        // ---- publish c (thread-packed, coalesced) ----
        *reinterpret_cast<float4*>(g_cbuf + rowoff + (tid << 2)) =
            make_float4(cleft[0][0], cleft[0][1], cleft[0][2], cleft[0][3]);
        *reinterpret_cast<float4*>(g_cbuf + rowoff + 2048 + (tid << 2)) =
            make_float4(cleft[1][0], cleft[1][1], cleft[1][2], cleft[1][3]);

        // ---- stage x(w+1) into left[nxt] x-cols (disjoint from h cols) ----
        if (w + 1 < Ww) {
            const int e = w + 1;
            if ((e & 3) == 0)
                xq = *reinterpret_cast<const float4*>(xrow + (fx ? (124 - e) : e));
            const int ei = (e & 3) ^ xm;
            float s01 = (ei & 1) ? xq.y : xq.x;
            float s23 = (ei & 1) ? xq.w : xq.z;
            sA[(64 + nxt * 32 + sx_b) * ASTR + 128 + sx_ci] =
                __float2half((ei & 2) ? s23 : s01);
        }

        __syncwarp();   // warp's own STS h(w) visible to warp

        // ---- per-warp h publish: own 8 channels, all 32 batches (canonical layout) ----
        {
            uint4 v = *reinterpret_cast<const uint4*>(
                sA + (64 + nxt * 32 + lane) * ASTR + (wid << 3));
            *reinterpret_cast<uint4*>(g_hbuf + rowoff + (size_t)lane * 128 + (wid << 3)) = v;
        }

        __syncwarp();   // order all lanes' STG before lane0's release
        if (lane == 0) st_rel(&g_pw[bid][wid], (unsigned)(w + 1));
    }

    // ---- output epilogue: transpose f16 row history -> coalesced fp32 stores ----
    __half* tile = reinterpret_cast<__half*>(smem);   // reuse sB region
    float* outp = out + (size_t)d * Oc * Bsz * Hh * Ww;
    __syncthreads();
#pragma unroll 1
    for (int b = 0; b < Bsz; ++b) {
#pragma unroll 1
        for (int idx = tid; idx < 128 * 64; idx += THREADS) {   // u32 units: 128 w x 64
            int wq = idx >> 6, s = idx & 63;
            unsigned v = *reinterpret_cast<const unsigned*>(
                g_hbuf + ((size_t)bid * Ww + wq) * (Bsz * Oc) + b * Oc + s * 2);
            *reinterpret_cast<unsigned*>(tile + wq * TTS + s * 2) = v;
        }
        __syncthreads();
#pragma unroll 1
        for (int idx = tid; idx < 128 * 128; idx += THREADS) {
            int ch = idx >> 7, pw = idx & 127;
            int ww = fx ? (127 - pw) : pw;
            outp[(((size_t)ch * Bsz + b) * Hh + ph) * Ww + pw] =
                __half2float(tile[ww * TTS + ch]);
        }
        __syncthreads();
    }
}

// ---------------- launch ----------------
extern "C" void kernel_launch(void* const* d_in, const int* in_sizes, int n_in,
                              void* d_out, int out_size)
{
    const float* x     = (const float*)d_in[0];
    const float* w_ii  = (const float*)d_in[1];
    const float* w_hi  = (const float*)d_in[2];
    const float* b_i   = (const float*)d_in[3];
    const float* w_if  = (const float*)d_in[4];
    const float* w_hf  = (const float*)d_in[5];
    const float* b_f   = (const float*)d_in[6];
    const float* w_ig  = (const float*)d_in[7];
    const float* w_hg  = (const float*)d_in[8];
    const float* b_g   = (const float*)d_in[9];
    const float* w_io  = (const float*)d_in[10];
    const float* w_ho  = (const float*)d_in[11];
    const float* b_o   = (const float*)d_in[12];
    const float* wsum  = (const float*)d_in[13];
    const float* biasv = (const float*)d_in[14];
    float* out = (float*)d_out;

    cudaFuncSetAttribute(mdlstm_kernel,
                         cudaFuncAttributeMaxDynamicSharedMemorySize, SMEM_TOTAL);

    init_progress_kernel<<<2, 1024>>>();
    mdlstm_kernel<<<128, THREADS, SMEM_TOTAL>>>(
        x, w_ii, w_hi, b_i, w_if, w_hf, b_f, w_ig, w_hg, b_g,
        w_io, w_ho, b_o, wsum, biasv, out);
}

// round 13
// speedup vs baseline: 1.0939x; 1.0939x over previous
#include <cuda_runtime.h>
#include <cuda_fp16.h>
#include <cstddef>
#include <cstdint>

// ---------------- problem constants ----------------
#define Bsz   32
#define CINc  16
#define Hh    32
#define Ww    128
#define Oc    128
#define NTOT  512          // 128 channels x 4 gates, n = ch*4 + gate
#define ASTR  168          // A half-stride (84 words; LDSM 8-row banks distinct)
#define BSTR  152          // B half-stride (76 words; LDSM 8-row banks distinct)
#define THREADS 512

// ---------------- shared memory layout (bytes) ----------------
// A rows: 0-31 top buf0, 32-63 top buf1, 64-95 left buf0, 96-127 left buf1
// (left buffers carry h cols 0-127 and x cols 128-143)
#define OFF_B     0
#define SZ_B      (NTOT * BSTR * 2)            // 155648
#define OFF_A     (OFF_B + SZ_B)               // 155648
#define SZ_A      (128 * ASTR * 2)             // 43008
#define OFF_BIAS  (OFF_A + SZ_A)               // 198656
#define SZ_BIAS   (5 * Oc * 4)                 // 2560
#define SMEM_TOTAL (OFF_BIAS + SZ_BIAS)        // 201216

// transpose tile stride (halves); 69 words odd -> conflict-free strided reads
#define TTS 138

// ---------------- global scratch ----------------
// g_hbuf: warp-blocked [bid][w][chBlock(16)][b(32)][8ch]  (4096 halves per column)
// g_cbuf: thread-packed [bid][w][p*2048 + tid*4 + nt]
__device__ __align__(256) __half  g_hbuf[(size_t)128 * 128 * 32 * 128];
__device__ __align__(256) float   g_cbuf[(size_t)128 * 128 * 32 * 128];
__device__ unsigned               g_progress[128];

// ---------------- helpers ----------------
__device__ __forceinline__ float tnhf(float x) {
    float y;
    asm("tanh.approx.f32 %0, %1;" : "=f"(y) : "f"(x));
    return y;
}
__device__ __forceinline__ float sigf(float x) {
    return fmaf(tnhf(0.5f * x), 0.5f, 0.5f);
}
__device__ __forceinline__ unsigned ld_acq(const unsigned* p) {
    unsigned v;
    asm volatile("ld.acquire.gpu.global.b32 %0, [%1];" : "=r"(v) : "l"(p));
    return v;
}
__device__ __forceinline__ void st_rel(unsigned* p, unsigned v) {
    asm volatile("st.release.gpu.global.b32 [%0], %1;" :: "l"(p), "r"(v) : "memory");
}
__device__ __forceinline__ unsigned pack2h(float lo, float hi) {
    return (unsigned)__half_as_ushort(__float2half(lo))
         | ((unsigned)__half_as_ushort(__float2half(hi)) << 16);
}
__device__ __forceinline__ void mma16816(float* c, const unsigned* a, unsigned b0, unsigned b1) {
    asm volatile(
        "mma.sync.aligned.m16n8k16.row.col.f32.f16.f16.f32 "
        "{%0,%1,%2,%3}, {%4,%5,%6,%7}, {%8,%9}, {%0,%1,%2,%3};"
        : "+f"(c[0]), "+f"(c[1]), "+f"(c[2]), "+f"(c[3])
        : "r"(a[0]), "r"(a[1]), "r"(a[2]), "r"(a[3]), "r"(b0), "r"(b1));
}
__device__ __forceinline__ void ldsm_x4(unsigned* r, unsigned addr) {
    asm volatile(
        "ldmatrix.sync.aligned.m8n8.x4.shared.b16 {%0,%1,%2,%3}, [%4];"
        : "=r"(r[0]), "=r"(r[1]), "=r"(r[2]), "=r"(r[3]) : "r"(addr));
}

__global__ void init_progress_kernel() {
    if (threadIdx.x < 128) g_progress[threadIdx.x] = 0u;
}

// ---------------- main persistent kernel: one CTA per (direction, row) ----------------
__global__ void __launch_bounds__(THREADS, 1) mdlstm_kernel(
    const float* __restrict__ x,
    const float* __restrict__ w_ii, const float* __restrict__ w_hi, const float* __restrict__ b_i,
    const float* __restrict__ w_if, const float* __restrict__ w_hf, const float* __restrict__ b_f,
    const float* __restrict__ w_ig, const float* __restrict__ w_hg, const float* __restrict__ b_g,
    const float* __restrict__ w_io, const float* __restrict__ w_ho, const float* __restrict__ b_o,
    const float* __restrict__ wsum, const float* __restrict__ biasv,
    float* __restrict__ out)
{
    extern __shared__ char smem[];
    __half* sB    = reinterpret_cast<__half*>(smem + OFF_B);
    __half* sA    = reinterpret_cast<__half*>(smem + OFF_A);
    float*  sBias = reinterpret_cast<float*>(smem + OFF_BIAS);

    const int tid  = threadIdx.x;
    const int lane = tid & 31;
    const int wid  = tid >> 5;          // 0..15
    const int bid  = blockIdx.x;
    const int d    = bid >> 5;
    const int r    = bid & 31;
    const bool fx  = (d & 1) != 0;
    const bool fy  = (d & 2) != 0;
    const int  ph  = fy ? (Hh - 1 - r) : r;

    // ---- stage weights: sB[n][k], n = ch*4 + gate ----
    {
        const float* whArr[4] = {w_hi, w_hf, w_hg, w_ho};
        const float* wiArr[4] = {w_ii, w_if, w_ig, w_io};
        for (int gate = 0; gate < 4; ++gate) {
            const float* wh = whArr[gate] + (size_t)d * Oc * Oc;
            for (int idx = tid; idx < Oc * Oc; idx += THREADS) {
                int ch = idx >> 7, k = idx & 127;
                sB[(ch * 4 + gate) * BSTR + k] = __float2half(wh[idx]);
            }
            const float* wi = wiArr[gate] + (size_t)d * Oc * CINc;
            for (int idx = tid; idx < Oc * CINc; idx += THREADS) {
                int ch = idx >> 4, k = idx & 15;
                sB[(ch * 4 + gate) * BSTR + 128 + k] = __float2half(wi[idx]);
            }
        }
        const float* bArr[4] = {b_i, b_f, b_g, b_o};
        sBias[tid] = bArr[tid >> 7][(size_t)d * Oc + (tid & 127)];
        if (tid < 128) sBias[512 + tid] = biasv[(size_t)d * Oc + tid];
        // zero left buf0 h cols (read at w=0)
        for (int idx = tid; idx < 32 * 128; idx += THREADS) {
            int b = idx >> 7, c = idx & 127;
            sA[(64 + b) * ASTR + c] = __float2half(0.f);
        }
        if (r == 0) {   // h_top = 0 forever: zero both top buffers
            for (int idx = tid; idx < 64 * 128; idx += THREADS) {
                int b = idx >> 7, c = idx & 127;
                sA[b * ASTR + c] = __float2half(0.f);
            }
        }
    }
    const float ws0 = wsum[d * 2 + 0];
    const float ws1 = wsum[d * 2 + 1];

    const int g = lane >> 2, t = lane & 3;
    const bool oddt = (t & 1) != 0;
    const bool hiT  = (t >> 1) != 0;     // owns odd channel offsets

    // per-thread epilogue ownership: ch = chB + nt*2, bb = bbB + p*16
    const int chB = (wid << 3) + (t >> 1);
    const int bbB = g + (oddt ? 8 : 0);
    const int n0  = wid << 5;                        // warp's 32 n-cols
    const int sx_b = tid >> 4, sx_ci = tid & 15;     // h_top/x staging map
    const int bb_pub = g + (oddt ? 8 : 0) + (hiT ? 16 : 0);   // published h row

    // ldmatrix per-lane address roles
    const unsigned sAu = (unsigned)__cvta_generic_to_shared(sA);
    const unsigned sBu = (unsigned)__cvta_generic_to_shared(sB);
    const int aro  = (lane & 7) + ((lane >> 3) & 1) * 8;
    const int ako  = (lane >> 4) * 8;
    const unsigned aAtop0  = sAu + (unsigned)((aro * ASTR + ako) * 2);          // +tb*32 rows
    const unsigned aAleft0 = sAu + (unsigned)(((64 + aro) * ASTR + ako) * 2);   // +cur*32 rows
    const unsigned aBU     = sBu + (unsigned)(((n0 + ((lane >> 4) & 1) * 8 + (lane & 7)) * BSTR
                                               + ((lane >> 3) & 1) * 8) * 2);

    float cleft[2][4];
#pragma unroll
    for (int p = 0; p < 2; ++p)
#pragma unroll
        for (int nt = 0; nt < 4; ++nt) cleft[p][nt] = 0.f;

    unsigned avail = 0;
    const float* xrow = x + (size_t)tid * (Hh * Ww) + (size_t)ph * Ww;
    const int xm = fx ? 3 : 0;

    // prologue: stage x(0) into left buf0 x-cols
    float4 xq = *reinterpret_cast<const float4*>(xrow + (fx ? 124 : 0));
    {
        const int e = 0 ^ xm;
        float s01 = (e & 1) ? xq.y : xq.x;
        float s23 = (e & 1) ? xq.w : xq.z;
        sA[(64 + sx_b) * ASTR + 128 + sx_ci] = __float2half((e & 2) ? s23 : s01);
    }
    __syncthreads();

#pragma unroll 1
    for (int w = 0; w < Ww; ++w) {
        const int cur = w & 1, nxt = cur ^ 1, tb = w & 1;
        const size_t rowoff = ((size_t)bid * Ww + w) * (Bsz * Oc);
        const size_t topoff = rowoff - (size_t)Ww * (Bsz * Oc);

        // ---- head: poll single flag (cached), LDG h_top/c_top, stage h_top ----
        float ctop_[2][4];
        if (r > 0) {
            if (avail <= (unsigned)w) {
                avail = ld_acq(&g_progress[bid - 1]);
                while (avail <= (unsigned)w) { __nanosleep(32); avail = ld_acq(&g_progress[bid - 1]); }
            }
            // blocked layout: [chBlock=tid&15][b=tid>>4][8]
            uint4 htop_v = *reinterpret_cast<const uint4*>(
                g_hbuf + topoff + (size_t)(tid & 15) * 256 + (size_t)(tid >> 4) * 8);
            float4 q0 = *reinterpret_cast<const float4*>(g_cbuf + topoff + (tid << 2));
            float4 q1 = *reinterpret_cast<const float4*>(g_cbuf + topoff + 2048 + (tid << 2));
            ctop_[0][0] = q0.x; ctop_[0][1] = q0.y; ctop_[0][2] = q0.z; ctop_[0][3] = q0.w;
            ctop_[1][0] = q1.x; ctop_[1][1] = q1.y; ctop_[1][2] = q1.z; ctop_[1][3] = q1.w;
            // double-buffered top staging: safe pre-barrier (readers of top[tb] were step w-2)
            *reinterpret_cast<uint4*>(sA + (tb * 32 + sx_b) * ASTR + sx_ci * 8) = htop_v;
        } else {
#pragma unroll
            for (int p = 0; p < 2; ++p)
#pragma unroll
                for (int nt = 0; nt < 4; ++nt) ctop_[p][nt] = 0.f;
        }
        __syncthreads();   // S_A

        const unsigned aAleftU = aAleft0 + (unsigned)(cur * (32 * ASTR * 2));
        const unsigned aAtopU  = aAtop0  + (unsigned)(tb  * (32 * ASTR * 2));

        // ================= pass L: LEFT branch (left[cur]; k=8 = x cols) =================
        float htp[2][4];
        {
            float acc[2][4][4];
#pragma unroll
            for (int mt = 0; mt < 2; ++mt)
#pragma unroll
                for (int nt = 0; nt < 4; ++nt)
#pragma unroll
                    for (int q = 0; q < 4; ++q) acc[mt][nt][q] = 0.f;

#pragma unroll
            for (int k = 0; k < 9; ++k) {
                unsigned a0[4], a1[4], bp0[4], bp1[4];
                ldsm_x4(a0, aAleftU + (unsigned)(k * 32));
                ldsm_x4(a1, aAleftU + (unsigned)(16 * ASTR * 2 + k * 32));
                ldsm_x4(bp0, aBU + (unsigned)(k * 32));
                ldsm_x4(bp1, aBU + (unsigned)(16 * BSTR * 2 + k * 32));
                mma16816(acc[0][0], a0, bp0[0], bp0[1]);
                mma16816(acc[0][1], a0, bp0[2], bp0[3]);
                mma16816(acc[0][2], a0, bp1[0], bp1[1]);
                mma16816(acc[0][3], a0, bp1[2], bp1[3]);
                mma16816(acc[1][0], a1, bp0[0], bp0[1]);
                mma16816(acc[1][1], a1, bp0[2], bp0[3]);
                mma16816(acc[1][2], a1, bp1[0], bp1[1]);
                mma16816(acc[1][3], a1, bp1[2], bp1[3]);
            }
#pragma unroll
            for (int p = 0; p < 2; ++p) {
#pragma unroll
                for (int nt = 0; nt < 4; ++nt) {
                    float* c1 = acc[p][nt];
                    float rA = __shfl_xor_sync(0xffffffffu, oddt ? c1[0] : c1[2], 1);
                    float rB = __shfl_xor_sync(0xffffffffu, oddt ? c1[1] : c1[3], 1);
                    float pi, pf, pg, po;
                    if (!oddt) { pi = c1[0]; pf = c1[1]; pg = rA;    po = rB; }
                    else       { pi = rA;    pf = rB;    pg = c1[2]; po = c1[3]; }
                    const int ch = chB + nt * 2;
                    const float i1 = sigf(pi + sBias[ch]);
                    const float f1 = sigf(pf + sBias[128 + ch]);
                    const float g1 = tnhf(pg + sBias[256 + ch]);
                    const float o1 = sigf(po + sBias[384 + ch]);
                    const float cn1 = f1 * cleft[p][nt] + i1 * g1;
                    htp[p][nt]   = o1 * tnhf(cn1);
                    cleft[p][nt] = cn1;                 // cn1 carrier
                }
            }
        }

        // ================= pass T: TOP branch (top[tb]; k=8 from left[cur] x cols) ========
        float ht_s[2][4];
        {
            float acc[2][4][4];
#pragma unroll
            for (int mt = 0; mt < 2; ++mt)
#pragma unroll
                for (int nt = 0; nt < 4; ++nt)
#pragma unroll
                    for (int q = 0; q < 4; ++q) acc[mt][nt][q] = 0.f;

#pragma unroll
            for (int k = 0; k < 9; ++k) {
                const unsigned ab = (k < 8) ? (aAtopU + (unsigned)(k * 32))
                                            : (aAleftU + (unsigned)(8 * 32));
                unsigned a0[4], a1[4], bp0[4], bp1[4];
                ldsm_x4(a0, ab);
                ldsm_x4(a1, ab + (unsigned)(16 * ASTR * 2));
                ldsm_x4(bp0, aBU + (unsigned)(k * 32));
                ldsm_x4(bp1, aBU + (unsigned)(16 * BSTR * 2 + k * 32));
                mma16816(acc[0][0], a0, bp0[0], bp0[1]);
                mma16816(acc[0][1], a0, bp0[2], bp0[3]);
                mma16816(acc[0][2], a0, bp1[0], bp1[1]);
                mma16816(acc[0][3], a0, bp1[2], bp1[3]);
                mma16816(acc[1][0], a1, bp0[0], bp0[1]);
                mma16816(acc[1][1], a1, bp0[2], bp0[3]);
                mma16816(acc[1][2], a1, bp1[0], bp1[1]);
                mma16816(acc[1][3], a1, bp1[2], bp1[3]);
            }
#pragma unroll
            for (int p = 0; p < 2; ++p) {
#pragma unroll
                for (int nt = 0; nt < 4; ++nt) {
                    float* c0 = acc[p][nt];
                    float rA = __shfl_xor_sync(0xffffffffu, oddt ? c0[0] : c0[2], 1);
                    float rB = __shfl_xor_sync(0xffffffffu, oddt ? c0[1] : c0[3], 1);
                    float pi, pf, pg, po;
                    if (!oddt) { pi = c0[0]; pf = c0[1]; pg = rA;    po = rB; }
                    else       { pi = rA;    pf = rB;    pg = c0[2]; po = c0[3]; }
                    const int ch = chB + nt * 2;
                    const float i0 = sigf(pi + sBias[ch]);
                    const float f0 = sigf(pf + sBias[128 + ch]);
                    const float g0 = tnhf(pg + sBias[256 + ch]);
                    const float o0 = sigf(po + sBias[384 + ch]);
                    const float cn0 = f0 * ctop_[p][nt] + i0 * g0;
                    const float h0  = o0 * tnhf(cn0);

                    const float bv = sBias[512 + ch];
                    const float ct = fmaf(ws0, cn0, fmaf(ws1, cleft[p][nt], bv));
                    const float ht = fmaf(ws0, h0,  fmaf(ws1, htp[p][nt],  bv));

                    cleft[p][nt] = ct;
                    ht_s[p][nt]  = ht;
                    const int bb = bbB + p * 16;
                    sA[(64 + nxt * 32 + bb) * ASTR + ch] = __float2half(ht);   // h_left
                }
            }
        }

        // ---- publish h(w): register shuffle-pack -> one coalesced uint4 per thread ----
        {
            // partner (lane^2) has the other channel parity for the same bbB
            float r0 = __shfl_xor_sync(0xffffffffu, hiT ? ht_s[0][0] : ht_s[1][0], 2);
            float r1 = __shfl_xor_sync(0xffffffffu, hiT ? ht_s[0][1] : ht_s[1][1], 2);
            float r2 = __shfl_xor_sync(0xffffffffu, hiT ? ht_s[0][2] : ht_s[1][2], 2);
            float r3 = __shfl_xor_sync(0xffffffffu, hiT ? ht_s[0][3] : ht_s[1][3], 2);
            const int myp = hiT ? 1 : 0;
            uint4 pk;
            {
                float e0 = hiT ? r0 : ht_s[myp][0], o0 = hiT ? ht_s[myp][0] : r0;
                float e1 = hiT ? r1 : ht_s[myp][1], o1 = hiT ? ht_s[myp][1] : r1;
                float e2 = hiT ? r2 : ht_s[myp][2], o2 = hiT ? ht_s[myp][2] : r2;
                float e3 = hiT ? r3 : ht_s[myp][3], o3 = hiT ? ht_s[myp][3] : r3;
                pk.x = pack2h(e0, o0);
                pk.y = pack2h(e1, o1);
                pk.z = pack2h(e2, o2);
                pk.w = pack2h(e3, o3);
            }
            // blocked layout: [chBlock=wid][b=bb_pub][8]; per-warp 512B contiguous
            *reinterpret_cast<uint4*>(g_hbuf + rowoff + (size_t)wid * 256 + (size_t)bb_pub * 8) = pk;
        }

        // ---- publish c (thread-packed, coalesced) ----
        *reinterpret_cast<float4*>(g_cbuf + rowoff + (tid << 2)) =
            make_float4(cleft[0][0], cleft[0][1], cleft[0][2], cleft[0][3]);
        *reinterpret_cast<float4*>(g_cbuf + rowoff + 2048 + (tid << 2)) =
            make_float4(cleft[1][0], cleft[1][1], cleft[1][2], cleft[1][3]);

        // ---- stage x(w+1) into left[nxt] x-cols (disjoint from h cols) ----
        if (w + 1 < Ww) {
            const int e = w + 1;
            if ((e & 3) == 0)
                xq = *reinterpret_cast<const float4*>(xrow + (fx ? (124 - e) : e));
            const int ei = (e & 3) ^ xm;
            float s01 = (ei & 1) ? xq.y : xq.x;
            float s23 = (ei & 1) ? xq.w : xq.z;
            sA[(64 + nxt * 32 + sx_b) * ASTR + 128 + sx_ci] =
                __float2half((ei & 2) ? s23 : s01);
        }

        __syncthreads();   // S_rel: all threads' h/c stores ordered before the release
        if (tid == 0) st_rel(&g_progress[bid], (unsigned)(w + 1));
    }

    // ---- output epilogue: transpose f16 row history -> coalesced fp32 stores ----
    // g_hbuf blocked layout: [w][chBlock][b][8]; out[d][ch][b][ph][pw], w = fx ? 127-pw : pw
    __half* tile = reinterpret_cast<__half*>(smem);   // reuse sB region
    float* outp = out + (size_t)d * Oc * Bsz * Hh * Ww;
    __syncthreads();
#pragma unroll 1
    for (int b = 0; b < Bsz; ++b) {
#pragma unroll 1
        for (int idx = tid; idx < 128 * 64; idx += THREADS) {   // u32 units: 128 w x 64 ch-pairs
            int wq = idx >> 6, s = idx & 63;
            // halves 2s..2s+1: block = s>>2, inner u32 = s&3
            unsigned v = *reinterpret_cast<const unsigned*>(
                g_hbuf + ((size_t)bid * Ww + wq) * (Bsz * Oc)
                       + (size_t)(s >> 2) * 256 + (size_t)b * 8 + (s & 3) * 2);
            *reinterpret_cast<unsigned*>(tile + wq * TTS + s * 2) = v;
        }
        __syncthreads();
#pragma unroll 1
        for (int idx = tid; idx < 128 * 128; idx += THREADS) {
            int ch = idx >> 7, pw = idx & 127;
            int ww = fx ? (127 - pw) : pw;
            outp[(((size_t)ch * Bsz + b) * Hh + ph) * Ww + pw] =
                __half2float(tile[ww * TTS + ch]);
        }
        __syncthreads();
    }
}

// ---------------- launch ----------------
extern "C" void kernel_launch(void* const* d_in, const int* in_sizes, int n_in,
                              void* d_out, int out_size)
{
    const float* x     = (const float*)d_in[0];
    const float* w_ii  = (const float*)d_in[1];
    const float* w_hi  = (const float*)d_in[2];
    const float* b_i   = (const float*)d_in[3];
    const float* w_if  = (const float*)d_in[4];
    const float* w_hf  = (const float*)d_in[5];
    const float* b_f   = (const float*)d_in[6];
    const float* w_ig  = (const float*)d_in[7];
    const float* w_hg  = (const float*)d_in[8];
    const float* b_g   = (const float*)d_in[9];
    const float* w_io  = (const float*)d_in[10];
    const float* w_ho  = (const float*)d_in[11];
    const float* b_o   = (const float*)d_in[12];
    const float* wsum  = (const float*)d_in[13];
    const float* biasv = (const float*)d_in[14];
    float* out = (float*)d_out;

    cudaFuncSetAttribute(mdlstm_kernel,
                         cudaFuncAttributeMaxDynamicSharedMemorySize, SMEM_TOTAL);

    init_progress_kernel<<<1, 128>>>();
    mdlstm_kernel<<<128, THREADS, SMEM_TOTAL>>>(
        x, w_ii, w_hi, b_i, w_if, w_hf, b_f, w_ig, w_hg, b_g,
        w_io, w_ho, b_o, wsum, biasv, out);
}